// round 10
// baseline (speedup 1.0000x reference)
#include <cuda_runtime.h>
#include <cuda_bf16.h>
#include <cstdint>

// Embedding gather using BOTH read engines concurrently:
//   out[row, :] = weight[ids[row], :],  row = 3072 B.
// 8 rows per CTA (1024 CTAs, 192 threads):
//   rows 0-3: TMA bulk G->S (thread 0, one mbarrier) -> SMEM -> STG
//   rows 4-7: direct LDG.128 gather by all 192 threads -> STG
// The LDG half executes while the TMA half is in flight, so gather
// requests are issued through the LSU/L1tex path AND the TMA path at
// the same time (every prior kernel plateaued at ~2.3TB/s on ONE engine).

static constexpr int DIM       = 768;
static constexpr int VEC       = DIM / 4;                 // 192 float4/row
static constexpr int ROW_BYTES = DIM * 4;                 // 3072
static constexpr int ROWS      = 8;
static constexpr int TMA_ROWS  = 4;                       // rows 0-3 via TMA
static constexpr int TMA_BYTES = TMA_ROWS * ROW_BYTES;    // 12288
static constexpr int THREADS   = VEC;                     // 192

__global__ __launch_bounds__(THREADS) void emb_dual_kernel(
    const int* __restrict__ ids,
    const float* __restrict__ weight,
    float* __restrict__ out)
{
    __shared__ __align__(128) unsigned char buf[TMA_BYTES];
    __shared__ __align__(8)  unsigned long long mbar;

    const int base = blockIdx.x * ROWS;
    const int t    = threadIdx.x;

    uint32_t sb = (uint32_t)__cvta_generic_to_shared(buf);
    uint32_t mb = (uint32_t)__cvta_generic_to_shared(&mbar);

    if (t == 0) {
        asm volatile("mbarrier.init.shared.b64 [%0], 1;" :: "r"(mb) : "memory");
        asm volatile("fence.proxy.async.shared::cta;" ::: "memory");
    }
    __syncthreads();   // init visible before any thread can wait

    // ---- TMA half: thread 0 launches 4 bulk gathers (async engine) ----
    if (t == 0) {
        int id[TMA_ROWS];
#pragma unroll
        for (int s = 0; s < TMA_ROWS; s++)
            id[s] = __ldg(&ids[base + s]);

        asm volatile("mbarrier.arrive.expect_tx.shared.b64 _, [%0], %1;"
                     :: "r"(mb), "r"(TMA_BYTES) : "memory");
#pragma unroll
        for (int s = 0; s < TMA_ROWS; s++) {
            const void* src = (const char*)weight + (size_t)id[s] * ROW_BYTES;
            asm volatile(
                "cp.async.bulk.shared::cta.global.mbarrier::complete_tx::bytes "
                "[%0], [%1], %2, [%3];"
                :: "r"(sb + s * ROW_BYTES), "l"(src), "r"(ROW_BYTES), "r"(mb)
                : "memory");
        }
    }

    const float4* w4 = (const float4*)weight;
    float4*       o4 = (float4*)out + (size_t)base * VEC;

    // ---- LDG half: rows 4-7 gathered by all threads, overlapping TMA ----
    {
        // Broadcast id loads (all lanes same addr -> single transaction each).
        int id[ROWS - TMA_ROWS];
#pragma unroll
        for (int k = 0; k < ROWS - TMA_ROWS; k++)
            id[k] = __ldg(&ids[base + TMA_ROWS + k]);

        float4 v[ROWS - TMA_ROWS];
#pragma unroll
        for (int k = 0; k < ROWS - TMA_ROWS; k++)
            v[k] = __ldg(&w4[(size_t)id[k] * VEC + t]);   // 4 independent LDG.128

#pragma unroll
        for (int k = 0; k < ROWS - TMA_ROWS; k++)
            o4[(TMA_ROWS + k) * VEC + t] = v[k];
    }

    // ---- drain TMA half and store rows 0-3 ----
    {
        uint32_t done = 0;
        while (!done) {
            asm volatile(
                "{\n\t.reg .pred p;\n\t"
                "mbarrier.try_wait.parity.acquire.cta.shared::cta.b64 p, [%1], 0, 0x989680;\n\t"
                "selp.b32 %0, 1, 0, p;\n\t}"
                : "=r"(done) : "r"(mb) : "memory");
        }
    }
    const float4* sbuf = (const float4*)buf;
#pragma unroll
    for (int k = 0; k < TMA_ROWS; k++)
        o4[k * VEC + t] = sbuf[k * VEC + t];
}

extern "C" void kernel_launch(void* const* d_in, const int* in_sizes, int n_in,
                              void* d_out, int out_size)
{
    const int*   ids    = (const int*)d_in[0];     // [8192] int32
    const float* weight = (const float*)d_in[1];   // [32000, 768] f32
    float*       out    = (float*)d_out;           // [8192, 768] f32

    const int n_rows = in_sizes[0];                // 8192
    const int n_ctas = n_rows / ROWS;              // 1024
    emb_dual_kernel<<<n_ctas, THREADS>>>(ids, weight, out);
}

// round 11
// speedup vs baseline: 1.2611x; 1.2611x over previous
#include <cuda_runtime.h>
#include <cuda_bf16.h>
#include <cstdint>

// Embedding gather, TMA G->S + wide STG drain, short-CTA shape:
//   out[row, :] = weight[ids[row], :],  row = 3072 B.
// 4 rows per CTA (2048 CTAs, 192 threads). Lanes 0-3 each own one row:
// coalesced id load, own mbarrier, own G->S bulk copy. Then ALL 192
// threads store each row out as it lands (1 float4/thread per row).
// Shorter per-CTA critical path + ~14 resident CTAs/SM (single wave).

static constexpr int DIM       = 768;
static constexpr int VEC       = DIM / 4;              // 192 float4/row
static constexpr int ROW_BYTES = DIM * 4;              // 3072
static constexpr int ROWS      = 4;
static constexpr int BUF_BYTES = ROWS * ROW_BYTES;     // 12288
static constexpr int THREADS   = VEC;                  // 192

__global__ __launch_bounds__(THREADS) void emb_kernel(
    const int* __restrict__ ids,
    const float* __restrict__ weight,
    float* __restrict__ out)
{
    __shared__ __align__(128) unsigned char buf[BUF_BYTES];
    __shared__ __align__(8)  unsigned long long mbar[ROWS];

    const int base = blockIdx.x * ROWS;
    const int t    = threadIdx.x;

    uint32_t sb  = (uint32_t)__cvta_generic_to_shared(buf);
    uint32_t mb0 = (uint32_t)__cvta_generic_to_shared(mbar);

    // Lane-per-row init + issue (lanes 0..3 of warp 0).
    if (t < ROWS) {
        uint32_t mb = mb0 + t * 8;
        asm volatile("mbarrier.init.shared.b64 [%0], 1;" :: "r"(mb) : "memory");
        asm volatile("fence.proxy.async.shared::cta;" ::: "memory");

        const int id = __ldg(&ids[base + t]);          // coalesced, 4 lanes

        asm volatile("mbarrier.arrive.expect_tx.shared.b64 _, [%0], %1;"
                     :: "r"(mb), "r"(ROW_BYTES) : "memory");
        const void* src = (const char*)weight + (size_t)id * ROW_BYTES;
        asm volatile(
            "cp.async.bulk.shared::cta.global.mbarrier::complete_tx::bytes "
            "[%0], [%1], %2, [%3];"
            :: "r"(sb + t * ROW_BYTES), "l"(src), "r"(ROW_BYTES), "r"(mb)
            : "memory");
    }
    __syncthreads();   // mbarrier init + issue visible to all store threads

    const float4* sbuf = (const float4*)buf;
    float4*       o4   = (float4*)out + (size_t)base * VEC;

    // Drain each row as it lands: all 192 threads, one float4 each.
#pragma unroll
    for (int r = 0; r < ROWS; r++) {
        uint32_t mb = mb0 + r * 8;
        uint32_t done = 0;
        while (!done) {
            asm volatile(
                "{\n\t.reg .pred p;\n\t"
                "mbarrier.try_wait.parity.acquire.cta.shared::cta.b64 p, [%1], 0, 0x989680;\n\t"
                "selp.b32 %0, 1, 0, p;\n\t}"
                : "=r"(done) : "r"(mb) : "memory");
        }
        o4[r * VEC + t] = sbuf[r * VEC + t];
    }
}

extern "C" void kernel_launch(void* const* d_in, const int* in_sizes, int n_in,
                              void* d_out, int out_size)
{
    const int*   ids    = (const int*)d_in[0];     // [8192] int32
    const float* weight = (const float*)d_in[1];   // [32000, 768] f32
    float*       out    = (float*)d_out;           // [8192, 768] f32

    const int n_rows = in_sizes[0];                // 8192
    const int n_ctas = n_rows / ROWS;              // 2048
    emb_kernel<<<n_ctas, THREADS>>>(ids, weight, out);
}